// round 1
// baseline (speedup 1.0000x reference)
#include <cuda_runtime.h>
#include <math.h>
#include <stddef.h>

#define BATCH   256
#define HID     1024
#define TSTEPS  256
#define NG      4096            // 4 * HID
#define KC      2048            // combined K (c part + h part)

// ---------------- device scratch (static, no allocations) ----------------
__device__ float d_WcatT[KC * NG];     // [k][n]: rows 0..1023 = W_c^T, rows 1024..2047 = W_hh^T  (32 MB)
__device__ float d_WihT [HID * NG];    // W_ih^T [o][n]                                           (16 MB)
__device__ float d_WfcT [HID * HID];   // W_fc^T [h][o]                                           (4 MB)
__device__ float d_biasF[NG];          // b_ih + b_hh + W_ih @ b_fc
__device__ float d_bias0[NG];          // b_ih + b_hh
__device__ float d_gates[BATCH * NG];  // per-step gate scratch                                   (4 MB)

__device__ __forceinline__ float sigf(float x) { return 1.0f / (1.0f + expf(-x)); }

// ---------------- transpose: src[R][C] -> dst[C][R] (dims multiples of 32) ----------------
__global__ void transpose_k(const float* __restrict__ src, float* __restrict__ dst, int R, int C) {
    __shared__ float tile[32][33];
    int c0 = blockIdx.x * 32, r0 = blockIdx.y * 32;
    int x = threadIdx.x, y = threadIdx.y;           // 32 x 8
    #pragma unroll
    for (int i = 0; i < 32; i += 8)
        tile[y + i][x] = src[(size_t)(r0 + y + i) * C + c0 + x];
    __syncthreads();
    #pragma unroll
    for (int i = 0; i < 32; i += 8)
        dst[(size_t)(c0 + y + i) * R + r0 + x] = tile[x][y + i];
}

// ---------------- W_comb: d_WcatT[h][n] = sum_o Wfc[o][h] * WihT[o][n]  (h<1024, n<4096) ----------------
__global__ void wcomb_kernel(const float* __restrict__ Wfc) {
    __shared__ float As[16][65];
    __shared__ float Bs[16][64];
    int n0 = blockIdx.x * 64;
    int m0 = blockIdx.y * 64;      // m = h
    int tid = threadIdx.x;
    int tx = tid & 15, ty = tid >> 4;
    int lk = tid >> 4;             // 0..15
    int lv = (tid & 15) * 4;       // 0,4,...,60
    float acc[4][4] = {};
    for (int kt = 0; kt < HID; kt += 16) {
        // A accessed [k][m]: Wfc[(kt+lk)*HID + m0+lv .. +3]  (contiguous in m)
        float4 a = *(const float4*)&Wfc[(size_t)(kt + lk) * HID + m0 + lv];
        As[lk][lv + 0] = a.x; As[lk][lv + 1] = a.y; As[lk][lv + 2] = a.z; As[lk][lv + 3] = a.w;
        float4 b = *(const float4*)&d_WihT[(size_t)(kt + lk) * NG + n0 + lv];
        *(float4*)&Bs[lk][lv] = b;
        __syncthreads();
        #pragma unroll
        for (int k = 0; k < 16; k++) {
            float a0 = As[k][ty * 4 + 0], a1 = As[k][ty * 4 + 1];
            float a2 = As[k][ty * 4 + 2], a3 = As[k][ty * 4 + 3];
            float4 bv = *(const float4*)&Bs[k][tx * 4];
            acc[0][0] += a0 * bv.x; acc[0][1] += a0 * bv.y; acc[0][2] += a0 * bv.z; acc[0][3] += a0 * bv.w;
            acc[1][0] += a1 * bv.x; acc[1][1] += a1 * bv.y; acc[1][2] += a1 * bv.z; acc[1][3] += a1 * bv.w;
            acc[2][0] += a2 * bv.x; acc[2][1] += a2 * bv.y; acc[2][2] += a2 * bv.z; acc[2][3] += a2 * bv.w;
            acc[3][0] += a3 * bv.x; acc[3][1] += a3 * bv.y; acc[3][2] += a3 * bv.z; acc[3][3] += a3 * bv.w;
        }
        __syncthreads();
    }
    #pragma unroll
    for (int i = 0; i < 4; i++) {
        int m = m0 + ty * 4 + i;
        float4 v = make_float4(acc[i][0], acc[i][1], acc[i][2], acc[i][3]);
        *(float4*)&d_WcatT[(size_t)m * NG + n0 + tx * 4] = v;
    }
}

// ---------------- fused biases ----------------
__global__ void bias_kernel(const float* __restrict__ Wih, const float* __restrict__ bih,
                            const float* __restrict__ bhh, const float* __restrict__ bfc) {
    int n = blockIdx.x * blockDim.x + threadIdx.x;   // 4096 threads
    const float* row = Wih + (size_t)n * HID;
    float s = 0.f;
    for (int o = 0; o < HID; o++) s += row[o] * bfc[o];
    float b0 = bih[n] + bhh[n];
    d_bias0[n] = b0;
    d_biasF[n] = b0 + s;
}

// ---------------- per-step gate GEMM: d_gates[m][n] = sum_k A[m][k] * WcatT[k][n] + bias[n] ----------------
// A[m][k] piecewise: k<1024 -> Ac (c_{t-1}), k>=1024 -> Ah (h_{t-1}); kstart=1024 at t=0 (i_0 = 0).
__global__ void gates_kernel(const float* __restrict__ Ac, const float* __restrict__ Ah,
                             size_t sA, int kstart, int useF) {
    __shared__ float As[16][65];
    __shared__ float Bs[16][64];
    int n0 = blockIdx.x * 64;
    int m0 = blockIdx.y * 64;
    int tid = threadIdx.x;
    int tx = tid & 15, ty = tid >> 4;
    int lmA = tid >> 2;            // 0..63
    int lkA = (tid & 3) * 4;       // 0,4,8,12
    int lkB = tid >> 4;            // 0..15
    int lnB = (tid & 15) * 4;
    float acc[4][4] = {};
    for (int kt = kstart; kt < KC; kt += 16) {
        const float* Aptr = (kt < HID)
            ? (Ac + (size_t)(m0 + lmA) * sA + kt + lkA)
            : (Ah + (size_t)(m0 + lmA) * sA + (kt - HID) + lkA);
        float4 a = *(const float4*)Aptr;
        As[lkA + 0][lmA] = a.x; As[lkA + 1][lmA] = a.y; As[lkA + 2][lmA] = a.z; As[lkA + 3][lmA] = a.w;
        float4 b = *(const float4*)&d_WcatT[(size_t)(kt + lkB) * NG + n0 + lnB];
        *(float4*)&Bs[lkB][lnB] = b;
        __syncthreads();
        #pragma unroll
        for (int k = 0; k < 16; k++) {
            float a0 = As[k][ty * 4 + 0], a1 = As[k][ty * 4 + 1];
            float a2 = As[k][ty * 4 + 2], a3 = As[k][ty * 4 + 3];
            float4 bv = *(const float4*)&Bs[k][tx * 4];
            acc[0][0] += a0 * bv.x; acc[0][1] += a0 * bv.y; acc[0][2] += a0 * bv.z; acc[0][3] += a0 * bv.w;
            acc[1][0] += a1 * bv.x; acc[1][1] += a1 * bv.y; acc[1][2] += a1 * bv.z; acc[1][3] += a1 * bv.w;
            acc[2][0] += a2 * bv.x; acc[2][1] += a2 * bv.y; acc[2][2] += a2 * bv.z; acc[2][3] += a2 * bv.w;
            acc[3][0] += a3 * bv.x; acc[3][1] += a3 * bv.y; acc[3][2] += a3 * bv.z; acc[3][3] += a3 * bv.w;
        }
        __syncthreads();
    }
    const float* bias = useF ? d_biasF : d_bias0;
    float4 bz = *(const float4*)&bias[n0 + tx * 4];
    #pragma unroll
    for (int i = 0; i < 4; i++) {
        int m = m0 + ty * 4 + i;
        float4 v = make_float4(acc[i][0] + bz.x, acc[i][1] + bz.y, acc[i][2] + bz.z, acc[i][3] + bz.w);
        *(float4*)&d_gates[(size_t)m * NG + n0 + tx * 4] = v;
    }
}

// ---------------- elementwise LSTM cell; writes h_states[:,t,:] and c_states[:,t,:] into d_out ----------------
__global__ void cell_kernel(const float* __restrict__ cvec, float* __restrict__ out, int t) {
    const size_t SO = (size_t)BATCH * TSTEPS * HID;
    int idx = blockIdx.x * blockDim.x + threadIdx.x;   // BATCH*HID
    int b = idx >> 10, d = idx & (HID - 1);
    const float* g = d_gates + (size_t)b * NG + d;
    float ig = g[0], fg = g[HID], gg = g[2 * HID], og = g[3 * HID];
    float cp = (t == 0) ? cvec[idx]
                        : out[SO + (size_t)b * TSTEPS * HID + (size_t)(t - 1) * HID + d];
    float cn = sigf(fg) * cp + sigf(ig) * tanhf(gg);
    float hn = sigf(og) * tanhf(cn);
    size_t o = (size_t)b * TSTEPS * HID + (size_t)t * HID + d;
    out[o]      = hn;   // h_states
    out[SO + o] = cn;   // c_states
}

// ---------------- final batched GEMM: outputs[r][o] = sum_h cst[r][h] * WfcT[h][o] + bfc[o] ----------------
__global__ void final_kernel(const float* __restrict__ A, const float* __restrict__ bfc,
                             float* __restrict__ C) {
    __shared__ float As[16][65];
    __shared__ float Bs[16][64];
    int n0 = blockIdx.x * 64;
    int m0 = blockIdx.y * 64;
    int tid = threadIdx.x;
    int tx = tid & 15, ty = tid >> 4;
    int lmA = tid >> 2;
    int lkA = (tid & 3) * 4;
    int lkB = tid >> 4;
    int lnB = (tid & 15) * 4;
    float acc[4][4] = {};
    for (int kt = 0; kt < HID; kt += 16) {
        float4 a = *(const float4*)&A[(size_t)(m0 + lmA) * HID + kt + lkA];
        As[lkA + 0][lmA] = a.x; As[lkA + 1][lmA] = a.y; As[lkA + 2][lmA] = a.z; As[lkA + 3][lmA] = a.w;
        float4 b = *(const float4*)&d_WfcT[(size_t)(kt + lkB) * HID + n0 + lnB];
        *(float4*)&Bs[lkB][lnB] = b;
        __syncthreads();
        #pragma unroll
        for (int k = 0; k < 16; k++) {
            float a0 = As[k][ty * 4 + 0], a1 = As[k][ty * 4 + 1];
            float a2 = As[k][ty * 4 + 2], a3 = As[k][ty * 4 + 3];
            float4 bv = *(const float4*)&Bs[k][tx * 4];
            acc[0][0] += a0 * bv.x; acc[0][1] += a0 * bv.y; acc[0][2] += a0 * bv.z; acc[0][3] += a0 * bv.w;
            acc[1][0] += a1 * bv.x; acc[1][1] += a1 * bv.y; acc[1][2] += a1 * bv.z; acc[1][3] += a1 * bv.w;
            acc[2][0] += a2 * bv.x; acc[2][1] += a2 * bv.y; acc[2][2] += a2 * bv.z; acc[2][3] += a2 * bv.w;
            acc[3][0] += a3 * bv.x; acc[3][1] += a3 * bv.y; acc[3][2] += a3 * bv.z; acc[3][3] += a3 * bv.w;
        }
        __syncthreads();
    }
    float4 bz = *(const float4*)&bfc[n0 + tx * 4];
    #pragma unroll
    for (int i = 0; i < 4; i++) {
        int m = m0 + ty * 4 + i;
        float4 v = make_float4(acc[i][0] + bz.x, acc[i][1] + bz.y, acc[i][2] + bz.z, acc[i][3] + bz.w);
        *(float4*)&C[(size_t)m * HID + n0 + tx * 4] = v;
    }
}

// ---------------- launch ----------------
extern "C" void kernel_launch(void* const* d_in, const int* in_sizes, int n_in,
                              void* d_out, int out_size) {
    (void)in_sizes; (void)n_in; (void)out_size;
    const float* c_vector = (const float*)d_in[0];
    const float* W_ih     = (const float*)d_in[1];
    const float* W_hh     = (const float*)d_in[2];
    const float* b_ih     = (const float*)d_in[3];
    const float* b_hh     = (const float*)d_in[4];
    const float* W_fc     = (const float*)d_in[5];
    const float* b_fc     = (const float*)d_in[6];
    float* out = (float*)d_out;

    float *pWihT, *pWcatT, *pWfcT;
    cudaGetSymbolAddress((void**)&pWihT, d_WihT);
    cudaGetSymbolAddress((void**)&pWcatT, d_WcatT);
    cudaGetSymbolAddress((void**)&pWfcT, d_WfcT);

    // Precompute (all on the capture stream, ordered):
    transpose_k<<<dim3(HID / 32, NG / 32), dim3(32, 8)>>>(W_ih, pWihT, NG, HID);
    transpose_k<<<dim3(HID / 32, NG / 32), dim3(32, 8)>>>(W_hh, pWcatT + (size_t)HID * NG, NG, HID);
    transpose_k<<<dim3(HID / 32, HID / 32), dim3(32, 8)>>>(W_fc, pWfcT, HID, HID);
    wcomb_kernel<<<dim3(NG / 64, HID / 64), 256>>>(W_fc);
    bias_kernel<<<NG / 256, 256>>>(W_ih, b_ih, b_hh, b_fc);

    const size_t SO = (size_t)BATCH * TSTEPS * HID;

    for (int t = 0; t < TSTEPS; t++) {
        if (t == 0) {
            // gates = h_{-1} @ W_hh^T + (b_ih + b_hh); h_{-1} = c_vector (contiguous, stride HID)
            gates_kernel<<<dim3(NG / 64, BATCH / 64), 256>>>(c_vector, c_vector, (size_t)HID, HID, 0);
        } else {
            const float* cprev = out + SO + (size_t)(t - 1) * HID;  // c_states[:, t-1, :]
            const float* hprev = out + (size_t)(t - 1) * HID;       // h_states[:, t-1, :]
            gates_kernel<<<dim3(NG / 64, BATCH / 64), 256>>>(cprev, hprev, (size_t)TSTEPS * HID, 0, 1);
        }
        cell_kernel<<<BATCH * HID / 256, 256>>>(c_vector, out, t);
    }

    // outputs = c_states @ W_fc^T + b_fc  (one big parallel GEMM over all timesteps)
    final_kernel<<<dim3(HID / 64, (BATCH * TSTEPS) / 64), 256>>>(out + SO, b_fc, out + 2 * SO);
}

// round 4
// speedup vs baseline: 3.4932x; 3.4932x over previous
#include <cuda_runtime.h>
#include <math.h>
#include <stdint.h>
#include <stddef.h>

#define TSTEPS 256
#define HID    1024
#define NB     256
#define KC     2048
#define NG     4096
#define SOFF   ((size_t)NB * TSTEPS * HID)

// ---------------- static device scratch ----------------
__device__ __align__(256) float d_Wt[(size_t)NG * KC];   // reordered [n'=4d+g][k] combined weights (tf32-rounded)
__device__ __align__(256) float d_A0[(size_t)NB * KC];   // A ping-pong [b][k]: k<1024 = c part, else h part
__device__ __align__(256) float d_A1[(size_t)NB * KC];
__device__ __align__(256) float d_Wf[(size_t)HID * HID]; // tf32-rounded W_fc [o][h]
__device__ float d_b0[NG];                               // reordered b_ih+b_hh            (t = 0)
__device__ float d_bF[NG];                               // reordered + W_ih@b_fc folded   (t >= 1)

__device__ __forceinline__ float sigf(float x) { return 1.0f / (1.0f + expf(-x)); }
__device__ __forceinline__ float tf32r(float x) {
    uint32_t u; asm("cvt.rna.tf32.f32 %0, %1;" : "=r"(u) : "f"(x));
    return __uint_as_float(u);
}
__device__ __forceinline__ uint32_t smem_u32(const void* p) {
    uint32_t a;
    asm("{ .reg .u64 t; cvta.to.shared.u64 t, %1; cvt.u32.u64 %0, t; }" : "=r"(a) : "l"(p));
    return a;
}

#define CPA(dst, src) asm volatile("cp.async.cg.shared.global [%0], [%1], 16;" :: "r"(dst), "l"(src))
#define CPC()         asm volatile("cp.async.commit_group;" ::: "memory")
#define CPW(n)        asm volatile("cp.async.wait_group %0;" :: "n"(n) : "memory")

#define MMA8(d, a, b) asm volatile( \
    "mma.sync.aligned.m16n8k8.row.col.f32.tf32.tf32.f32 " \
    "{%0,%1,%2,%3}, {%4,%5,%6,%7}, {%8,%9}, {%0,%1,%2,%3};" \
    : "+f"((d)[0]), "+f"((d)[1]), "+f"((d)[2]), "+f"((d)[3]) \
    : "r"((a)[0]), "r"((a)[1]), "r"((a)[2]), "r"((a)[3]), "r"((b)[0]), "r"((b)[1]))

// ---------------- GEMM tiling ----------------
#define BM     64
#define BN     128
#define BK     32
#define STAGES 3
#define ASTR   36                 // padded smem row stride (floats) -> conflict-free frag loads
#define ASZ    (BM * ASTR)        // 2304 floats
#define BSZ    (BN * ASTR)        // 4608 floats
#define STG_F  (ASZ + BSZ)        // 6912 floats / stage
#define SMEM_BYTES (STAGES * STG_F * 4)   // 82944 B (>= BM*BN*4 = 32768 epilogue reuse)

// ================= unified tf32 mma.sync GEMM =================
// MODE 0: per-step gates GEMM + fused LSTM cell epilogue
// MODE 1: plain GEMM + bias epilogue (final outputs)
template<int MODE>
__global__ void __launch_bounds__(256) gemm_k(
    const float* __restrict__ Ag, long long lda,
    const float* __restrict__ Bg, long long ldb,
    const float* __restrict__ pb,
    const float* __restrict__ pc, long long cstride,
    float* __restrict__ pout, float* __restrict__ pAw,
    int t, int ktot)
{
    extern __shared__ __align__(16) float sm[];
    const int tid = threadIdx.x;
    const int n0 = blockIdx.x * BN;
    const int m0 = blockIdx.y * BM;
    const int w = tid >> 5, lane = tid & 31;
    const int wm = w & 1, wn = w >> 1;          // 2 x 4 warp grid
    const int gid = lane >> 2, tig = lane & 3;

    const float* Atile = Ag + (size_t)m0 * lda;
    const float* Btile = Bg + (size_t)n0 * ldb;
    const uint32_t sbase = smem_u32(sm);

    float acc[2][4][4];
    #pragma unroll
    for (int i = 0; i < 2; i++)
        #pragma unroll
        for (int j = 0; j < 4; j++)
            #pragma unroll
            for (int q = 0; q < 4; q++) acc[i][j][q] = 0.f;

    const int KT = ktot / BK;

    // ---- stage loader (all 256 threads) ----
    auto load_stage = [&](int stage, int kt) {
        uint32_t sa = sbase + (uint32_t)(stage * STG_F) * 4u;
        uint32_t sb = sa + (uint32_t)ASZ * 4u;
        #pragma unroll
        for (int i = 0; i < 2; i++) {
            int idx = tid + i * 256;            // 0..511
            int r = idx >> 3, c = (idx & 7) * 4;
            CPA(sa + (uint32_t)(r * ASTR + c) * 4u, Atile + (size_t)r * lda + kt + c);
        }
        #pragma unroll
        for (int i = 0; i < 4; i++) {
            int idx = tid + i * 256;            // 0..1023
            int r = idx >> 3, c = (idx & 7) * 4;
            CPA(sb + (uint32_t)(r * ASTR + c) * 4u, Btile + (size_t)r * ldb + kt + c);
        }
        CPC();
    };

    load_stage(0, 0);
    load_stage(1, BK);

    for (int kt = 0; kt < KT; kt++) {
        CPW(STAGES - 2);
        __syncthreads();
        // issue next load (into the stage computed in the PREVIOUS iteration; barrier above makes it safe)
        int kn = kt + STAGES - 1;
        if (kn < KT) load_stage(kn % STAGES, kn * BK); else CPC();

        const float* sA = sm + (size_t)(kt % STAGES) * STG_F;
        const float* sB = sA + ASZ;
        #pragma unroll
        for (int ks = 0; ks < 4; ks++) {
            int k0 = ks * 8;
            uint32_t a[2][4], b[4][2];
            #pragma unroll
            for (int mt = 0; mt < 2; mt++) {
                int mr = wm * 32 + mt * 16 + gid;
                a[mt][0] = __float_as_uint(sA[(mr)     * ASTR + k0 + tig]);
                a[mt][1] = __float_as_uint(sA[(mr + 8) * ASTR + k0 + tig]);
                a[mt][2] = __float_as_uint(sA[(mr)     * ASTR + k0 + tig + 4]);
                a[mt][3] = __float_as_uint(sA[(mr + 8) * ASTR + k0 + tig + 4]);
            }
            #pragma unroll
            for (int nt = 0; nt < 4; nt++) {
                int nc = wn * 32 + nt * 8 + gid;
                b[nt][0] = __float_as_uint(sB[nc * ASTR + k0 + tig]);
                b[nt][1] = __float_as_uint(sB[nc * ASTR + k0 + tig + 4]);
            }
            #pragma unroll
            for (int mt = 0; mt < 2; mt++)
                #pragma unroll
                for (int nt = 0; nt < 4; nt++)
                    MMA8(acc[mt][nt], a[mt], b[nt]);
        }
        __syncthreads();
    }

    // ---- stash C tile to smem (reuse pipeline smem) ----
    float* Cs = sm;
    #pragma unroll
    for (int mt = 0; mt < 2; mt++) {
        int row = wm * 32 + mt * 16 + gid;
        #pragma unroll
        for (int nt = 0; nt < 4; nt++) {
            int col = wn * 32 + nt * 8 + 2 * tig;
            *(float2*)&Cs[(row)     * BN + col] = make_float2(acc[mt][nt][0], acc[mt][nt][1]);
            *(float2*)&Cs[(row + 8) * BN + col] = make_float2(acc[mt][nt][2], acc[mt][nt][3]);
        }
    }
    __syncthreads();

    if (MODE == 0) {
        // fused LSTM cell: n' = 4d+g -> all 4 gates contiguous in Cs
        #pragma unroll
        for (int i = 0; i < 8; i++) {
            int e = tid + i * 256;               // 0..2047
            int b = e >> 5, dl = e & 31;
            float4 g  = *(float4*)&Cs[b * BN + 4 * dl];
            float4 bz = *(const float4*)&pb[n0 + 4 * dl];
            float ig = g.x + bz.x, fg = g.y + bz.y, gg = g.z + bz.z, og = g.w + bz.w;
            int bg = m0 + b;
            int d  = (n0 >> 2) + dl;
            float cp = pc[(size_t)bg * cstride + d];
            float cn = sigf(fg) * cp + sigf(ig) * tanhf(gg);
            float hn = sigf(og) * tanhf(cn);
            size_t ro = (size_t)bg * (TSTEPS * HID) + (size_t)t * HID + d;
            pout[ro]        = hn;                // h_states
            pout[SOFF + ro] = cn;                // c_states
            size_t ao = (size_t)bg * KC + d;     // next-step A (tf32 RNA)
            pAw[ao]        = tf32r(cn);
            pAw[ao + 1024] = tf32r(hn);
        }
    } else {
        #pragma unroll
        for (int i = 0; i < 8; i++) {
            int e = tid + i * 256;
            int b = e >> 5, j4 = (e & 31) * 4;
            float4 v  = *(float4*)&Cs[b * BN + j4];
            float4 bz = *(const float4*)&pb[n0 + j4];
            size_t ro = (size_t)(m0 + b) * HID + n0 + j4;
            *(float4*)&pout[ro] = make_float4(v.x + bz.x, v.y + bz.y, v.z + bz.z, v.w + bz.w);
        }
    }
}

// ================= prep kernels =================
// W_c = W_ih @ W_fc (exact fp32), stored reordered + tf32-rounded into d_Wt[:, 0:1024]
__global__ void prep_wc(const float* __restrict__ Wih, const float* __restrict__ Wfc) {
    __shared__ float As[16][65];
    __shared__ float Bs[16][64];
    int n0 = blockIdx.x * 64;          // output k (0..1023)
    int m0 = blockIdx.y * 64;          // row of W_ih (gate-major n, 0..4095)
    int tid = threadIdx.x;
    int tx = tid & 15, ty = tid >> 4;
    int lmA = tid >> 2, lkA = (tid & 3) * 4;
    int lkB = tid >> 4, lnB = (tid & 15) * 4;
    float acc[4][4] = {};
    for (int kt = 0; kt < HID; kt += 16) {
        float4 a = *(const float4*)&Wih[(size_t)(m0 + lmA) * HID + kt + lkA];
        As[lkA + 0][lmA] = a.x; As[lkA + 1][lmA] = a.y; As[lkA + 2][lmA] = a.z; As[lkA + 3][lmA] = a.w;
        float4 bv4 = *(const float4*)&Wfc[(size_t)(kt + lkB) * HID + n0 + lnB];
        *(float4*)&Bs[lkB][lnB] = bv4;
        __syncthreads();
        #pragma unroll
        for (int k = 0; k < 16; k++) {
            float a0 = As[k][ty * 4 + 0], a1 = As[k][ty * 4 + 1];
            float a2 = As[k][ty * 4 + 2], a3 = As[k][ty * 4 + 3];
            float4 bv = *(const float4*)&Bs[k][tx * 4];
            acc[0][0] += a0 * bv.x; acc[0][1] += a0 * bv.y; acc[0][2] += a0 * bv.z; acc[0][3] += a0 * bv.w;
            acc[1][0] += a1 * bv.x; acc[1][1] += a1 * bv.y; acc[1][2] += a1 * bv.z; acc[1][3] += a1 * bv.w;
            acc[2][0] += a2 * bv.x; acc[2][1] += a2 * bv.y; acc[2][2] += a2 * bv.z; acc[2][3] += a2 * bv.w;
            acc[3][0] += a3 * bv.x; acc[3][1] += a3 * bv.y; acc[3][2] += a3 * bv.z; acc[3][3] += a3 * bv.w;
        }
        __syncthreads();
    }
    #pragma unroll
    for (int i = 0; i < 4; i++) {
        int n = m0 + ty * 4 + i;
        int npr = 4 * (n & 1023) + (n >> 10);
        *(float4*)&d_Wt[(size_t)npr * KC + n0 + tx * 4] =
            make_float4(tf32r(acc[i][0]), tf32r(acc[i][1]), tf32r(acc[i][2]), tf32r(acc[i][3]));
    }
}

__global__ void prep_whh(const float* __restrict__ Whh) {
    int idx = blockIdx.x * blockDim.x + threadIdx.x;     // NG*HID/4
    int n = idx >> 8, k = (idx & 255) * 4;
    float4 v = *(const float4*)&Whh[(size_t)n * HID + k];
    int npr = 4 * (n & 1023) + (n >> 10);
    *(float4*)&d_Wt[(size_t)npr * KC + HID + k] =
        make_float4(tf32r(v.x), tf32r(v.y), tf32r(v.z), tf32r(v.w));
}

__global__ void prep_wfc(const float* __restrict__ Wfc) {
    int idx = blockIdx.x * blockDim.x + threadIdx.x;     // HID*HID/4
    float4 v = *(const float4*)&Wfc[(size_t)idx * 4];
    *(float4*)&d_Wf[(size_t)idx * 4] = make_float4(tf32r(v.x), tf32r(v.y), tf32r(v.z), tf32r(v.w));
}

__global__ void prep_bias(const float* __restrict__ Wih, const float* __restrict__ bih,
                          const float* __restrict__ bhh, const float* __restrict__ bfc) {
    int n = (blockIdx.x * blockDim.x + threadIdx.x) >> 5;   // one warp per n
    int lane = threadIdx.x & 31;
    const float* row = Wih + (size_t)n * HID;
    float s = 0.f;
    for (int o = lane; o < HID; o += 32) s += row[o] * bfc[o];
    #pragma unroll
    for (int off = 16; off; off >>= 1) s += __shfl_xor_sync(0xFFFFFFFFu, s, off);
    if (lane == 0) {
        int npr = 4 * (n & 1023) + (n >> 10);
        float b0 = bih[n] + bhh[n];
        d_b0[npr] = b0;
        d_bF[npr] = b0 + s;
    }
}

__global__ void prep_A0(const float* __restrict__ cvec) {
    int idx = blockIdx.x * blockDim.x + threadIdx.x;     // NB*KC
    int b = idx >> 11, k = idx & 2047;
    d_A0[idx] = (k < 1024) ? 0.f : tf32r(cvec[(size_t)b * HID + (k - 1024)]);
}

// ================= host =================
extern "C" void kernel_launch(void* const* d_in, const int* in_sizes, int n_in,
                              void* d_out, int out_size) {
    (void)in_sizes; (void)n_in; (void)out_size;
    const float* c_vector = (const float*)d_in[0];
    const float* W_ih     = (const float*)d_in[1];
    const float* W_hh     = (const float*)d_in[2];
    const float* b_ih     = (const float*)d_in[3];
    const float* b_hh     = (const float*)d_in[4];
    const float* W_fc     = (const float*)d_in[5];
    const float* b_fc     = (const float*)d_in[6];
    float* out = (float*)d_out;

    float *pWt, *pA0, *pA1, *pWf, *pb0, *pbF;
    cudaGetSymbolAddress((void**)&pWt, d_Wt);
    cudaGetSymbolAddress((void**)&pA0, d_A0);
    cudaGetSymbolAddress((void**)&pA1, d_A1);
    cudaGetSymbolAddress((void**)&pWf, d_Wf);
    cudaGetSymbolAddress((void**)&pb0, d_b0);
    cudaGetSymbolAddress((void**)&pbF, d_bF);

    cudaFuncSetAttribute(gemm_k<0>, cudaFuncAttributeMaxDynamicSharedMemorySize, SMEM_BYTES);
    cudaFuncSetAttribute(gemm_k<1>, cudaFuncAttributeMaxDynamicSharedMemorySize, SMEM_BYTES);

    prep_wc  <<<dim3(HID / 64, NG / 64), 256>>>(W_ih, W_fc);
    prep_whh <<<(NG * HID / 4) / 256, 256>>>(W_hh);
    prep_wfc <<<(HID * HID / 4) / 256, 256>>>(W_fc);
    prep_bias<<<NG * 32 / 1024, 1024>>>(W_ih, b_ih, b_hh, b_fc);
    prep_A0  <<<(NB * KC) / 256, 256>>>(c_vector);

    for (int t = 0; t < TSTEPS; t++) {
        const float* Ain = (t & 1) ? pA1 : pA0;
        float*       Aw  = (t & 1) ? pA0 : pA1;
        const float* pc  = (t == 0) ? c_vector : (out + SOFF + (size_t)(t - 1) * HID);
        long long    cs  = (t == 0) ? (long long)HID : (long long)TSTEPS * HID;
        gemm_k<0><<<dim3(NG / BN, NB / BM), 256, SMEM_BYTES>>>(
            Ain, (long long)KC, pWt, (long long)KC,
            (t == 0) ? pb0 : pbF,
            pc, cs, out, Aw, t, KC);
    }

    // outputs = c_states @ W_fc^T + b_fc : rows r = b*T + t (matches out layout), A = c_states fp32 (HW tf32 truncation)
    gemm_k<1><<<dim3(HID / BN, (NB * TSTEPS) / BM), 256, SMEM_BYTES>>>(
        out + SOFF, (long long)HID, pWf, (long long)HID,
        b_fc, (const float*)0, 0, out + 2 * SOFF, (float*)0, 0, HID);
}

// round 7
// speedup vs baseline: 4.2808x; 1.2255x over previous
#include <cuda_runtime.h>
#include <math.h>
#include <stdint.h>
#include <stddef.h>

#define TSTEPS 256
#define HID    1024
#define NB     256
#define KC     2048
#define NG     4096
#define SOFF   ((size_t)NB * TSTEPS * HID)

// ---------------- static device scratch ----------------
__device__ __align__(256) float d_Wt[(size_t)NG * KC];    // reordered [n'=4d+g][k]; k<1024: W_c (tf32), k>=1024: W_hh (tf32)
__device__ __align__(256) float d_Ac0[(size_t)NB * HID];  // c-part A ping-pong (tf32-rounded)
__device__ __align__(256) float d_Ac1[(size_t)NB * HID];
__device__ __align__(256) float d_Ah0[(size_t)NB * HID];  // h-part A ping-pong (tf32-rounded)
__device__ __align__(256) float d_Ah1[(size_t)NB * HID];
__device__ __align__(256) float d_Wf[(size_t)HID * HID];  // tf32-rounded W_fc [o][h]
__device__ __align__(256) float d_P[2 * (size_t)NB * NG]; // split-K partial gate sums
__device__ float d_b0[NG];                                // reordered b_ih+b_hh          (t = 0)
__device__ float d_bF[NG];                                // reordered + W_ih@b_fc folded (t >= 1)

__device__ __forceinline__ float sigf(float x) { return 1.0f / (1.0f + expf(-x)); }
__device__ __forceinline__ float tf32r(float x) {
    uint32_t u; asm("cvt.rna.tf32.f32 %0, %1;" : "=r"(u) : "f"(x));
    return __uint_as_float(u);
}
__device__ __forceinline__ uint32_t smem_u32(const void* p) {
    uint32_t a;
    asm("{ .reg .u64 t; cvta.to.shared.u64 t, %1; cvt.u32.u64 %0, t; }" : "=r"(a) : "l"(p));
    return a;
}

#define CPA(dst, src) asm volatile("cp.async.cg.shared.global [%0], [%1], 16;" :: "r"(dst), "l"(src))
#define CPC()         asm volatile("cp.async.commit_group;" ::: "memory")
#define CPW(n)        asm volatile("cp.async.wait_group %0;" :: "n"(n) : "memory")

#define MMA8(d, a, b) asm volatile( \
    "mma.sync.aligned.m16n8k8.row.col.f32.tf32.tf32.f32 " \
    "{%0,%1,%2,%3}, {%4,%5,%6,%7}, {%8,%9}, {%0,%1,%2,%3};" \
    : "+f"((d)[0]), "+f"((d)[1]), "+f"((d)[2]), "+f"((d)[3]) \
    : "r"((a)[0]), "r"((a)[1]), "r"((a)[2]), "r"((a)[3]), "r"((b)[0]), "r"((b)[1]))

// ---------------- GEMM tiling: CTA 128x128, 4 warps (warp tile 64x64), BK=32, 3 stages ----------------
#define BM     128
#define BN     128
#define BK     32
#define STAGES 3
#define ASTR   36
#define ASZ    (BM * ASTR)            // 4608 floats
#define BSZ    (BN * ASTR)            // 4608 floats
#define STG_F  (ASZ + BSZ)            // 9216 floats / stage
#define SMEM_BYTES (STAGES * STG_F * 4)   // 110592 B; Cs tile (64KB) reuses this

// ================= tf32 mma.sync GEMM =================
// MODE 0: split-K gates GEMM -> raw partials to pP (blockIdx.z picks K-half)
// MODE 1: plain GEMM + bias (final outputs)
template<int MODE>
__global__ void __launch_bounds__(128) gemm_k(
    const float* __restrict__ Ac, const float* __restrict__ Ah, long long lda,
    const float* __restrict__ Bg, long long ldb,
    const float* __restrict__ pb,
    float* __restrict__ pout, long long ldo, int ktot)
{
    extern __shared__ __align__(16) float sm[];
    const int tid = threadIdx.x;
    const int n0 = blockIdx.x * BN;
    const int m0 = blockIdx.y * BM;
    const int kz = blockIdx.z;
    const int w = tid >> 5, lane = tid & 31;
    const int wm = w & 1, wn = w >> 1;          // 2 x 2 warp grid, warp tile 64x64
    const int gid = lane >> 2, tig = lane & 3;

    const float* Ag = (MODE == 0) ? (kz ? Ah : Ac) : Ac;
    const float* Bb = Bg + ((MODE == 0) ? kz * 1024 : 0);
    float* po = pout + ((MODE == 0) ? (size_t)kz * NB * NG : 0);

    const float* Atile = Ag + (size_t)m0 * lda;
    const float* Btile = Bb + (size_t)n0 * ldb;
    const uint32_t sbase = smem_u32(sm);

    float acc[4][8][4];
    #pragma unroll
    for (int i = 0; i < 4; i++)
        #pragma unroll
        for (int j = 0; j < 8; j++)
            #pragma unroll
            for (int q = 0; q < 4; q++) acc[i][j][q] = 0.f;

    const int KT = ktot / BK;

    auto load_stage = [&](int stage, int kt) {
        uint32_t sa = sbase + (uint32_t)(stage * STG_F) * 4u;
        uint32_t sb = sa + (uint32_t)ASZ * 4u;
        #pragma unroll
        for (int i = 0; i < 8; i++) {
            int idx = tid + i * 128;            // 0..1023
            int r = idx >> 3, c = (idx & 7) * 4;
            CPA(sa + (uint32_t)(r * ASTR + c) * 4u, Atile + (size_t)r * lda + kt + c);
        }
        #pragma unroll
        for (int i = 0; i < 8; i++) {
            int idx = tid + i * 128;
            int r = idx >> 3, c = (idx & 7) * 4;
            CPA(sb + (uint32_t)(r * ASTR + c) * 4u, Btile + (size_t)r * ldb + kt + c);
        }
        CPC();
    };

    load_stage(0, 0);
    load_stage(1, BK);

    for (int kt = 0; kt < KT; kt++) {
        CPW(STAGES - 2);
        __syncthreads();
        int kn = kt + STAGES - 1;
        if (kn < KT) load_stage(kn % STAGES, kn * BK); else CPC();

        const float* sA = sm + (size_t)(kt % STAGES) * STG_F;
        const float* sB = sA + ASZ;
        #pragma unroll
        for (int ks = 0; ks < 4; ks++) {
            int k0 = ks * 8;
            uint32_t a[4][4], b[8][2];
            #pragma unroll
            for (int mt = 0; mt < 4; mt++) {
                int mr = wm * 64 + mt * 16 + gid;
                a[mt][0] = __float_as_uint(sA[(mr)     * ASTR + k0 + tig]);
                a[mt][1] = __float_as_uint(sA[(mr + 8) * ASTR + k0 + tig]);
                a[mt][2] = __float_as_uint(sA[(mr)     * ASTR + k0 + tig + 4]);
                a[mt][3] = __float_as_uint(sA[(mr + 8) * ASTR + k0 + tig + 4]);
            }
            #pragma unroll
            for (int nt = 0; nt < 8; nt++) {
                int nc = wn * 64 + nt * 8 + gid;
                b[nt][0] = __float_as_uint(sB[nc * ASTR + k0 + tig]);
                b[nt][1] = __float_as_uint(sB[nc * ASTR + k0 + tig + 4]);
            }
            #pragma unroll
            for (int mt = 0; mt < 4; mt++)
                #pragma unroll
                for (int nt = 0; nt < 8; nt++)
                    MMA8(acc[mt][nt], a[mt], b[nt]);
        }
        __syncthreads();
    }

    // ---- stash C tile to smem, then coalesced float4 stores ----
    float* Cs = sm;
    #pragma unroll
    for (int mt = 0; mt < 4; mt++) {
        int row = wm * 64 + mt * 16 + gid;
        #pragma unroll
        for (int nt = 0; nt < 8; nt++) {
            int col = wn * 64 + nt * 8 + 2 * tig;
            *(float2*)&Cs[(row)     * BN + col] = make_float2(acc[mt][nt][0], acc[mt][nt][1]);
            *(float2*)&Cs[(row + 8) * BN + col] = make_float2(acc[mt][nt][2], acc[mt][nt][3]);
        }
    }
    __syncthreads();

    #pragma unroll
    for (int i = 0; i < 32; i++) {
        int e = tid + i * 128;                  // 0..4095 float4 slots
        int r = e >> 5, c4 = (e & 31) * 4;
        float4 v = *(float4*)&Cs[r * BN + c4];
        if (MODE == 1) {
            float4 bz = *(const float4*)&pb[n0 + c4];
            v = make_float4(v.x + bz.x, v.y + bz.y, v.z + bz.z, v.w + bz.w);
        }
        *(float4*)&po[(size_t)(m0 + r) * ldo + n0 + c4] = v;
    }
}

// ================= combine + LSTM cell =================
__global__ void __launch_bounds__(256) cell_k(
    const float* __restrict__ cvec, const float* __restrict__ pb,
    float* __restrict__ pout, float* __restrict__ pAc, float* __restrict__ pAh, int t)
{
    int e = blockIdx.x * blockDim.x + threadIdx.x;  // 0 .. NB*HID
    int b = e >> 10, d = e & 1023;
    float4 g0 = *(const float4*)&d_P[(size_t)b * NG + 4 * d];
    float4 g1 = *(const float4*)&d_P[(size_t)NB * NG + (size_t)b * NG + 4 * d];
    float4 bz = *(const float4*)&pb[4 * d];
    float ig = g0.x + g1.x + bz.x;
    float fg = g0.y + g1.y + bz.y;
    float gg = g0.z + g1.z + bz.z;
    float og = g0.w + g1.w + bz.w;
    float cp = (t == 0) ? cvec[e]
                        : pout[SOFF + (size_t)b * (TSTEPS * HID) + (size_t)(t - 1) * HID + d];
    float cn = sigf(fg) * cp + sigf(ig) * tanhf(gg);
    float hn = sigf(og) * tanhf(cn);
    size_t ro = (size_t)b * (TSTEPS * HID) + (size_t)t * HID + d;
    pout[ro]        = hn;
    pout[SOFF + ro] = cn;
    pAc[e] = tf32r(cn);
    pAh[e] = tf32r(hn);
}

// ================= prep kernels =================
// W_c = W_ih @ W_fc (exact fp32 SIMT), stored reordered + tf32-rounded into d_Wt[:, 0:1024]
__global__ void prep_wc(const float* __restrict__ Wih, const float* __restrict__ Wfc) {
    __shared__ float As[16][65];
    __shared__ float Bs[16][64];
    int n0 = blockIdx.x * 64;          // output k (0..1023)
    int m0 = blockIdx.y * 64;          // row of W_ih (gate-major n, 0..4095)
    int tid = threadIdx.x;
    int tx = tid & 15, ty = tid >> 4;
    int lmA = tid >> 2, lkA = (tid & 3) * 4;
    int lkB = tid >> 4, lnB = (tid & 15) * 4;
    float acc[4][4] = {};
    for (int kt = 0; kt < HID; kt += 16) {
        float4 a = *(const float4*)&Wih[(size_t)(m0 + lmA) * HID + kt + lkA];
        As[lkA + 0][lmA] = a.x; As[lkA + 1][lmA] = a.y; As[lkA + 2][lmA] = a.z; As[lkA + 3][lmA] = a.w;
        float4 bv4 = *(const float4*)&Wfc[(size_t)(kt + lkB) * HID + n0 + lnB];
        *(float4*)&Bs[lkB][lnB] = bv4;
        __syncthreads();
        #pragma unroll
        for (int k = 0; k < 16; k++) {
            float a0 = As[k][ty * 4 + 0], a1 = As[k][ty * 4 + 1];
            float a2 = As[k][ty * 4 + 2], a3 = As[k][ty * 4 + 3];
            float4 bv = *(const float4*)&Bs[k][tx * 4];
            acc[0][0] += a0 * bv.x; acc[0][1] += a0 * bv.y; acc[0][2] += a0 * bv.z; acc[0][3] += a0 * bv.w;
            acc[1][0] += a1 * bv.x; acc[1][1] += a1 * bv.y; acc[1][2] += a1 * bv.z; acc[1][3] += a1 * bv.w;
            acc[2][0] += a2 * bv.x; acc[2][1] += a2 * bv.y; acc[2][2] += a2 * bv.z; acc[2][3] += a2 * bv.w;
            acc[3][0] += a3 * bv.x; acc[3][1] += a3 * bv.y; acc[3][2] += a3 * bv.z; acc[3][3] += a3 * bv.w;
        }
        __syncthreads();
    }
    #pragma unroll
    for (int i = 0; i < 4; i++) {
        int n = m0 + ty * 4 + i;
        int npr = 4 * (n & 1023) + (n >> 10);
        *(float4*)&d_Wt[(size_t)npr * KC + n0 + tx * 4] =
            make_float4(tf32r(acc[i][0]), tf32r(acc[i][1]), tf32r(acc[i][2]), tf32r(acc[i][3]));
    }
}

__global__ void prep_whh(const float* __restrict__ Whh) {
    int idx = blockIdx.x * blockDim.x + threadIdx.x;     // NG*HID/4
    int n = idx >> 8, k = (idx & 255) * 4;
    float4 v = *(const float4*)&Whh[(size_t)n * HID + k];
    int npr = 4 * (n & 1023) + (n >> 10);
    *(float4*)&d_Wt[(size_t)npr * KC + HID + k] =
        make_float4(tf32r(v.x), tf32r(v.y), tf32r(v.z), tf32r(v.w));
}

__global__ void prep_wfc(const float* __restrict__ Wfc) {
    int idx = blockIdx.x * blockDim.x + threadIdx.x;     // HID*HID/4
    float4 v = *(const float4*)&Wfc[(size_t)idx * 4];
    *(float4*)&d_Wf[(size_t)idx * 4] = make_float4(tf32r(v.x), tf32r(v.y), tf32r(v.z), tf32r(v.w));
}

__global__ void prep_bias(const float* __restrict__ Wih, const float* __restrict__ bih,
                          const float* __restrict__ bhh, const float* __restrict__ bfc) {
    int n = (blockIdx.x * blockDim.x + threadIdx.x) >> 5;
    int lane = threadIdx.x & 31;
    const float* row = Wih + (size_t)n * HID;
    float s = 0.f;
    for (int o = lane; o < HID; o += 32) s += row[o] * bfc[o];
    #pragma unroll
    for (int off = 16; off; off >>= 1) s += __shfl_xor_sync(0xFFFFFFFFu, s, off);
    if (lane == 0) {
        int npr = 4 * (n & 1023) + (n >> 10);
        float b0 = bih[n] + bhh[n];
        d_b0[npr] = b0;
        d_bF[npr] = b0 + s;
    }
}

__global__ void prep_A0(const float* __restrict__ cvec) {
    int idx = blockIdx.x * blockDim.x + threadIdx.x;     // NB*HID
    d_Ac0[idx] = 0.f;                    // i_0 = 0 -> c-part of step-0 A is zero
    d_Ah0[idx] = tf32r(cvec[idx]);       // h_{-1} = c_vector
}

// ================= host =================
extern "C" void kernel_launch(void* const* d_in, const int* in_sizes, int n_in,
                              void* d_out, int out_size) {
    (void)in_sizes; (void)n_in; (void)out_size;
    const float* c_vector = (const float*)d_in[0];
    const float* W_ih     = (const float*)d_in[1];
    const float* W_hh     = (const float*)d_in[2];
    const float* b_ih     = (const float*)d_in[3];
    const float* b_hh     = (const float*)d_in[4];
    const float* W_fc     = (const float*)d_in[5];
    const float* b_fc     = (const float*)d_in[6];
    float* out = (float*)d_out;

    float *pWt, *pAc0, *pAc1, *pAh0, *pAh1, *pWf, *pP, *pb0, *pbF;
    cudaGetSymbolAddress((void**)&pWt,  d_Wt);
    cudaGetSymbolAddress((void**)&pAc0, d_Ac0);
    cudaGetSymbolAddress((void**)&pAc1, d_Ac1);
    cudaGetSymbolAddress((void**)&pAh0, d_Ah0);
    cudaGetSymbolAddress((void**)&pAh1, d_Ah1);
    cudaGetSymbolAddress((void**)&pWf,  d_Wf);
    cudaGetSymbolAddress((void**)&pP,   d_P);
    cudaGetSymbolAddress((void**)&pb0,  d_b0);
    cudaGetSymbolAddress((void**)&pbF,  d_bF);

    cudaFuncSetAttribute(gemm_k<0>, cudaFuncAttributeMaxDynamicSharedMemorySize, SMEM_BYTES);
    cudaFuncSetAttribute(gemm_k<1>, cudaFuncAttributeMaxDynamicSharedMemorySize, SMEM_BYTES);

    prep_wc  <<<dim3(HID / 64, NG / 64), 256>>>(W_ih, W_fc);
    prep_whh <<<(NG * HID / 4) / 256, 256>>>(W_hh);
    prep_wfc <<<(HID * HID / 4) / 256, 256>>>(W_fc);
    prep_bias<<<NG * 32 / 1024, 1024>>>(W_ih, b_ih, b_hh, b_fc);
    prep_A0  <<<(NB * HID) / 256, 256>>>(c_vector);

    for (int t = 0; t < TSTEPS; t++) {
        const float* Ac = (t & 1) ? pAc1 : pAc0;
        const float* Ah = (t & 1) ? pAh1 : pAh0;
        float* Acw = (t & 1) ? pAc0 : pAc1;
        float* Ahw = (t & 1) ? pAh0 : pAh1;
        const float* pb = (t == 0) ? pb0 : pbF;
        gemm_k<0><<<dim3(NG / BN, NB / BM, 2), 128, SMEM_BYTES>>>(
            Ac, Ah, (long long)HID, pWt, (long long)KC,
            (const float*)0, pP, (long long)NG, 1024);
        cell_k<<<(NB * HID) / 256, 256>>>(c_vector, pb, out, Acw, Ahw, t);
    }

    // outputs = c_states @ W_fc^T + b_fc (rows r = b*T + t match the output layout)
    gemm_k<1><<<dim3(HID / BN, (NB * TSTEPS) / BM, 1), 128, SMEM_BYTES>>>(
        out + SOFF, (const float*)0, (long long)HID, pWf, (long long)HID,
        b_fc, out + 2 * SOFF, (long long)HID, 1024);
}